// round 1
// baseline (speedup 1.0000x reference)
#include <cuda_runtime.h>
#include <cstdint>
#include <cstddef>

#define D_MODEL 1024
#define N_HEADS 16
#define BATCH   4
#define SEQ     4096
#define MTOK    (BATCH*SEQ)      /* 16384 tokens */
#define DK      64
#define BHD     (BATCH*N_HEADS)  /* 64 scan chains */

// ---------------- scratch (device globals: allocation-free) ----------------
__device__ float g_xn  [(size_t)MTOK*D_MODEL];
__device__ float g_q   [(size_t)MTOK*D_MODEL];   // [bh][t][dk]
__device__ float g_k   [(size_t)MTOK*D_MODEL];
__device__ float g_v   [(size_t)MTOK*D_MODEL];
__device__ float g_a   [(size_t)MTOK*D_MODEL];
__device__ float g_o   [(size_t)MTOK*D_MODEL];   // token-major [m][n]
__device__ float g_beta[(size_t)BHD*SEQ];

__device__ __forceinline__ float sigf(float x) { return 1.0f/(1.0f + __expf(-x)); }

// ---------------- LayerNorm: one block per token row ----------------
__global__ __launch_bounds__(256) void ln_kernel(const float* __restrict__ x,
                                                 const float* __restrict__ gamma,
                                                 const float* __restrict__ beta) {
  __shared__ float sred[9];
  int m = blockIdx.x, tid = threadIdx.x;
  const float4* xr = (const float4*)(x + (size_t)m*D_MODEL);
  float4 v = xr[tid];
  float s = v.x + v.y + v.z + v.w;
  #pragma unroll
  for (int o = 16; o > 0; o >>= 1) s += __shfl_xor_sync(0xffffffffu, s, o);
  if ((tid & 31) == 0) sred[tid >> 5] = s;
  __syncthreads();
  if (tid < 32) {
    float t2 = (tid < 8) ? sred[tid] : 0.f;
    #pragma unroll
    for (int o = 4; o > 0; o >>= 1) t2 += __shfl_xor_sync(0xffffffffu, t2, o);
    if (tid == 0) sred[8] = t2;
  }
  __syncthreads();
  float mean = sred[8] * (1.0f/1024.0f);
  float dx = v.x - mean, dy = v.y - mean, dz = v.z - mean, dw = v.w - mean;
  float sq = dx*dx + dy*dy + dz*dz + dw*dw;
  __syncthreads();
  #pragma unroll
  for (int o = 16; o > 0; o >>= 1) sq += __shfl_xor_sync(0xffffffffu, sq, o);
  if ((tid & 31) == 0) sred[tid >> 5] = sq;
  __syncthreads();
  if (tid < 32) {
    float t2 = (tid < 8) ? sred[tid] : 0.f;
    #pragma unroll
    for (int o = 4; o > 0; o >>= 1) t2 += __shfl_xor_sync(0xffffffffu, t2, o);
    if (tid == 0) sred[8] = t2;
  }
  __syncthreads();
  float inv = rsqrtf(sred[8] * (1.0f/1024.0f) + 1e-5f);
  float4 g  = ((const float4*)gamma)[tid];
  float4 bb = ((const float4*)beta)[tid];
  float4 o4;
  o4.x = dx*inv*g.x + bb.x;
  o4.y = dy*inv*g.y + bb.y;
  o4.z = dz*inv*g.z + bb.z;
  o4.w = dw*inv*g.w + bb.w;
  ((float4*)(g_xn + (size_t)m*D_MODEL))[tid] = o4;
}

// ---------------- tiled fp32 GEMM 128x128x16, 256 thr, 8x8 microtile ----------------
// SEL 0..3: C = g_xn @ W  -> scatter to [bh][t][dk]  (SEL==3 applies sigmoid)
// SEL 4  : C = g_o  @ W + x -> d_out (token-major)
template<int SEL>
__global__ __launch_bounds__(256) void gemm_kernel(const float* __restrict__ W,
                                                   const float* __restrict__ xadd,
                                                   float* __restrict__ dout) {
  const float* A = (SEL == 4) ? g_o : g_xn;
  float* dst = (SEL == 0) ? g_q : (SEL == 1) ? g_k : (SEL == 2) ? g_v :
               (SEL == 3) ? g_a : dout;
  __shared__ float As[16][132];
  __shared__ float Bs[16][132];
  int tid = threadIdx.x;
  int bn = blockIdx.x, bm = blockIdx.y;
  int tx = tid & 15, ty = tid >> 4;
  int arow = tid >> 2, ac4 = (tid & 3) << 2;
  int brow = tid >> 5, bcol = (tid & 31) << 2;
  const float* Ag = A + (size_t)(bm*128 + arow)*D_MODEL + ac4;
  const float* Bg = W + (size_t)brow*D_MODEL + bn*128 + bcol;

  float acc[8][8];
  #pragma unroll
  for (int i = 0; i < 8; i++)
    #pragma unroll
    for (int j = 0; j < 8; j++) acc[i][j] = 0.f;

  float4 ra0 = *(const float4*)(Ag);
  float4 ra1 = *(const float4*)(Ag + (size_t)64*D_MODEL);
  float4 rb0 = *(const float4*)(Bg);
  float4 rb1 = *(const float4*)(Bg + (size_t)8*D_MODEL);

  for (int kk = 0; kk < D_MODEL; kk += 16) {
    As[ac4+0][arow]    = ra0.x; As[ac4+1][arow]    = ra0.y;
    As[ac4+2][arow]    = ra0.z; As[ac4+3][arow]    = ra0.w;
    As[ac4+0][arow+64] = ra1.x; As[ac4+1][arow+64] = ra1.y;
    As[ac4+2][arow+64] = ra1.z; As[ac4+3][arow+64] = ra1.w;
    *(float4*)&Bs[brow][bcol]   = rb0;
    *(float4*)&Bs[brow+8][bcol] = rb1;
    __syncthreads();
    if (kk + 16 < D_MODEL) {
      ra0 = *(const float4*)(Ag + kk + 16);
      ra1 = *(const float4*)(Ag + (size_t)64*D_MODEL + kk + 16);
      rb0 = *(const float4*)(Bg + (size_t)(kk+16)*D_MODEL);
      rb1 = *(const float4*)(Bg + (size_t)(kk+24)*D_MODEL);
    }
    #pragma unroll
    for (int k = 0; k < 16; k++) {
      float af[8], bf[8];
      *(float4*)&af[0] = *(const float4*)&As[k][ty*8];
      *(float4*)&af[4] = *(const float4*)&As[k][ty*8+4];
      *(float4*)&bf[0] = *(const float4*)&Bs[k][tx*8];
      *(float4*)&bf[4] = *(const float4*)&Bs[k][tx*8+4];
      #pragma unroll
      for (int i = 0; i < 8; i++)
        #pragma unroll
        for (int j = 0; j < 8; j++)
          acc[i][j] = fmaf(af[i], bf[j], acc[i][j]);
    }
    __syncthreads();
  }

  if (SEL < 4) {
    int n0 = bn*128 + tx*8;
    int h = n0 >> 6, e0 = n0 & 63;
    #pragma unroll
    for (int i = 0; i < 8; i++) {
      int m = bm*128 + ty*8 + i;
      int b = m >> 12, t = m & 4095;
      size_t base = ((size_t)(b*N_HEADS + h)*SEQ + t)*DK + e0;
      float4 v0, v1;
      if (SEL == 3) {
        v0 = make_float4(sigf(acc[i][0]), sigf(acc[i][1]), sigf(acc[i][2]), sigf(acc[i][3]));
        v1 = make_float4(sigf(acc[i][4]), sigf(acc[i][5]), sigf(acc[i][6]), sigf(acc[i][7]));
      } else {
        v0 = make_float4(acc[i][0], acc[i][1], acc[i][2], acc[i][3]);
        v1 = make_float4(acc[i][4], acc[i][5], acc[i][6], acc[i][7]);
      }
      *(float4*)&dst[base]   = v0;
      *(float4*)&dst[base+4] = v1;
    }
  } else {
    int n0 = bn*128 + tx*8;
    #pragma unroll
    for (int i = 0; i < 8; i++) {
      int m = bm*128 + ty*8 + i;
      size_t off = (size_t)m*D_MODEL + n0;
      float4 x0 = *(const float4*)&xadd[off];
      float4 x1 = *(const float4*)&xadd[off+4];
      float4 v0 = make_float4(acc[i][0]+x0.x, acc[i][1]+x0.y, acc[i][2]+x0.z, acc[i][3]+x0.w);
      float4 v1 = make_float4(acc[i][4]+x1.x, acc[i][5]+x1.y, acc[i][6]+x1.z, acc[i][7]+x1.w);
      *(float4*)&dst[off]   = v0;
      *(float4*)&dst[off+4] = v1;
    }
  }
}

// ---------------- beta head: one block per token, 16 dots over K=1024 ----------------
__global__ __launch_bounds__(128) void beta_kernel(const float* __restrict__ Wb) {
  __shared__ float red[16][128];
  int m = blockIdx.x, tid = threadIdx.x;
  float p[16];
  #pragma unroll
  for (int h = 0; h < 16; h++) p[h] = 0.f;
  const float* xrow = g_xn + (size_t)m*D_MODEL;
  for (int k = tid; k < D_MODEL; k += 128) {
    float xv = xrow[k];
    const float4* w = (const float4*)(Wb + (size_t)k*N_HEADS);
    float4 w0 = w[0], w1 = w[1], w2 = w[2], w3 = w[3];
    p[0]  = fmaf(xv, w0.x, p[0]);  p[1]  = fmaf(xv, w0.y, p[1]);
    p[2]  = fmaf(xv, w0.z, p[2]);  p[3]  = fmaf(xv, w0.w, p[3]);
    p[4]  = fmaf(xv, w1.x, p[4]);  p[5]  = fmaf(xv, w1.y, p[5]);
    p[6]  = fmaf(xv, w1.z, p[6]);  p[7]  = fmaf(xv, w1.w, p[7]);
    p[8]  = fmaf(xv, w2.x, p[8]);  p[9]  = fmaf(xv, w2.y, p[9]);
    p[10] = fmaf(xv, w2.z, p[10]); p[11] = fmaf(xv, w2.w, p[11]);
    p[12] = fmaf(xv, w3.x, p[12]); p[13] = fmaf(xv, w3.y, p[13]);
    p[14] = fmaf(xv, w3.z, p[14]); p[15] = fmaf(xv, w3.w, p[15]);
  }
  #pragma unroll
  for (int h = 0; h < 16; h++) red[h][tid] = p[h];
  __syncthreads();
  if (tid < 16) {
    float s = 0.f;
    for (int i = 0; i < 128; i++) s += red[tid][i];
    int b = m >> 12, t = m & 4095;
    g_beta[(size_t)(b*N_HEADS + tid)*SEQ + t] = sigf(s);
  }
}

// ---------------- delta-rule scan: 64 blocks (one per b,h), 128 threads ----------------
// thread (half, e): owns S[d, e] for d in [half*32, half*32+32); rank-1 step:
//   S1 = S + (b*v[e]) k ;  r[e] = sum_d ak[d] S1[d,e] ;  S2 = a.*S1 - (b r[e]) k ;
//   o[e] = sum_d q[d] S2[d,e]
__global__ __launch_bounds__(128) void scan_kernel(float* __restrict__ sfin, int write_state) {
  int bh = blockIdx.x;
  int tid = threadIdx.x;
  int e = tid & 63;
  int half = tid >> 6;
  int dbase = half * 32;

  float S[32];
  #pragma unroll
  for (int i = 0; i < 32; i++) S[i] = 0.f;

  __shared__ float4 sh4[64];   // {k, a*k, a, q}
  __shared__ float shr[128];
  __shared__ float sho[128];

  const float* qp = g_q + (size_t)bh * SEQ * DK;
  const float* kp = g_k + (size_t)bh * SEQ * DK;
  const float* ap = g_a + (size_t)bh * SEQ * DK;
  const float* vp = g_v + (size_t)bh * SEQ * DK;
  const float* bp = g_beta + (size_t)bh * SEQ;

  int b_idx = bh >> 4, h_idx = bh & 15;
  size_t obase = (size_t)b_idx * SEQ * D_MODEL + (size_t)h_idx * DK + e;

  // prefetch t=0
  float pq = 0.f, pk = 0.f, pa = 0.f;
  if (tid < 64) { pq = qp[tid]; pk = kp[tid]; pa = ap[tid]; }
  float pv = vp[e];
  float pb = bp[0];

  for (int t = 0; t < SEQ; t++) {
    if (tid < 64) sh4[tid] = make_float4(pk, pa*pk, pa, pq);
    float bt = pb, vt = pv;
    __syncthreads();                 // staging visible
    if (t + 1 < SEQ) {               // prefetch next step under compute
      int off = (t + 1) * DK;
      if (tid < 64) { pq = qp[off+tid]; pk = kp[off+tid]; pa = ap[off+tid]; }
      pv = vp[off + e];
      pb = bp[t + 1];
    }
    float bv = bt * vt;
    float r0 = 0.f, r1 = 0.f;
    #pragma unroll
    for (int dd = 0; dd < 32; dd += 2) {
      float4 f = sh4[dbase + dd];
      S[dd] = fmaf(bv, f.x, S[dd]);
      r0 = fmaf(f.y, S[dd], r0);
      float4 g = sh4[dbase + dd + 1];
      S[dd+1] = fmaf(bv, g.x, S[dd+1]);
      r1 = fmaf(g.y, S[dd+1], r1);
    }
    shr[tid] = r0 + r1;
    __syncthreads();                 // r partials visible
    float r = shr[e] + shr[e + 64];
    float nbr = -bt * r;
    float o0 = 0.f, o1 = 0.f;
    #pragma unroll
    for (int dd = 0; dd < 32; dd += 2) {
      float4 f = sh4[dbase + dd];
      float s0 = fmaf(nbr, f.x, f.z * S[dd]);
      S[dd] = s0;
      o0 = fmaf(f.w, s0, o0);
      float4 g = sh4[dbase + dd + 1];
      float s1 = fmaf(nbr, g.x, g.z * S[dd+1]);
      S[dd+1] = s1;
      o1 = fmaf(g.w, s1, o1);
    }
    sho[tid] = o0 + o1;
    __syncthreads();                 // o partials visible (also protects sh4 reuse)
    if (half == 0) g_o[obase + (size_t)t * D_MODEL] = sho[e] + sho[e + 64];
  }

  if (write_state) {
    #pragma unroll
    for (int dd = 0; dd < 32; dd++)
      sfin[(size_t)bh*DK*DK + (size_t)(dbase + dd)*DK + e] = S[dd];
  }
}

// ---------------- launch ----------------
extern "C" void kernel_launch(void* const* d_in, const int* in_sizes, int n_in,
                              void* d_out, int out_size) {
  (void)in_sizes; (void)n_in;
  const float* x     = (const float*)d_in[0];
  const float* Wq    = (const float*)d_in[1];
  const float* Wk    = (const float*)d_in[2];
  const float* Wv    = (const float*)d_in[3];
  const float* Wg    = (const float*)d_in[4];
  const float* Wbeta = (const float*)d_in[5];
  const float* Wo    = (const float*)d_in[6];
  const float* gamma = (const float*)d_in[7];
  const float* bln   = (const float*)d_in[8];
  float* out = (float*)d_out;

  ln_kernel<<<MTOK, 256>>>(x, gamma, bln);

  dim3 ggrid(D_MODEL/128, MTOK/128);   // (8, 128)
  gemm_kernel<0><<<ggrid, 256>>>(Wq, nullptr, nullptr);
  gemm_kernel<1><<<ggrid, 256>>>(Wk, nullptr, nullptr);
  gemm_kernel<2><<<ggrid, 256>>>(Wv, nullptr, nullptr);
  gemm_kernel<3><<<ggrid, 256>>>(Wg, nullptr, nullptr);
  beta_kernel<<<MTOK, 128>>>(Wbeta);

  int ws = (out_size >= MTOK*D_MODEL + BHD*DK*DK) ? 1 : 0;
  scan_kernel<<<BHD, 128>>>(out + (size_t)MTOK*D_MODEL, ws);

  gemm_kernel<4><<<ggrid, 256>>>(Wo, x, out);
}